// round 4
// baseline (speedup 1.0000x reference)
#include <cuda_runtime.h>
#include <stdint.h>

// IN:  (4, 64, 224, 224) fp32
// OUT: (4, 576, 223*223) fp32, plane ck = bc*9 + ki*3 + kj (bc = b*64+c)
// out[ck, e] = x[bc, e/223 + ki - 1, e%223 + kj - 1]  (0 if OOB)
// addr identity: (oh+ki-1)*224 + (ow+kj-1) = e + oh + (ki-1)*224 + (kj-1)
#define OSP    49729u            // 223*223
#define NPLANE 2304u             // 4*64*9
#define CHUNK  2048u             // elements per block (256 thr x 8)
#define NCHUNK 25u               // ceil((49729+31)/2048)

__global__ void __launch_bounds__(256) unfold_chunks(const float* __restrict__ x,
                                                     float* __restrict__ out) {
    unsigned ck = blockIdx.y;
    // block-uniform decomposition
    unsigned kj = ck % 3u;
    unsigned t  = ck / 3u;
    unsigned ki = t % 3u;
    unsigned bc = t / 3u;

    size_t   a0 = (size_t)ck * OSP;            // plane base (flat output)
    unsigned s  = (unsigned)(a0 & 31u);        // shift so chunks are 128B-aligned globally

    int base = (int)(blockIdx.x * CHUNK) - (int)s + (int)threadIdx.x;

    const float* __restrict__ srcp = x + (size_t)bc * (224u * 224u);
    int koff = ((int)ki - 1) * 224 + ((int)kj - 1);
    float* __restrict__ dst = out + a0;

#pragma unroll
    for (int i = 0; i < 8; ++i) {
        int e = base + 256 * i;
        if ((unsigned)e < OSP) {
            unsigned oh = (unsigned)e / 223u;          // umulhi sequence
            unsigned ow = (unsigned)e - oh * 223u;
            // valid iff ih=oh+ki-1 >= 0 and iw=ow+kj-1 >= 0 (upper bounds always hold)
            float v = 0.0f;
            if ((oh + ki) != 0u && (ow + kj) != 0u) {
                v = __ldg(srcp + (e + (int)oh + koff));
            }
            // full 128B lines per warp -> streaming store is safe; keeps the
            // 51MB input resident in L2 for its 9x read reuse
            __stcs(dst + e, v);
        }
    }
}

extern "C" void kernel_launch(void* const* d_in, const int* in_sizes, int n_in,
                              void* d_out, int out_size) {
    const float* x = (const float*)d_in[0];
    float* out = (float*)d_out;
    dim3 grid(NCHUNK, NPLANE);
    unfold_chunks<<<grid, 256>>>(x, out);
}

// round 5
// speedup vs baseline: 2.0038x; 2.0038x over previous
#include <cuda_runtime.h>
#include <stdint.h>

// IN:  x (4, 64, 224, 224) fp32
// OUT: (4, 576, 223*223) fp32, plane ck = bc*9 + ki*3 + kj
// out[ck, oh*223+ow] = x[bc, oh+ki-1, ow+kj-1] (0 if OOB)
#define OSP   49729u      // 223*223
#define ISTR  50176u      // 224*224

// Block: 9 warps = 9 (ki,kj) planes, one (bc, ih) input row staged in smem.
__global__ void __launch_bounds__(288) unfold_smem(const float* __restrict__ x,
                                                   float* __restrict__ out) {
    __shared__ float sbuf[232];           // [0..3]=0 pad | 224 row | [228..231] pad
    unsigned ih = blockIdx.x;             // 0..223
    unsigned bc = blockIdx.y;             // 0..255
    unsigned tid = threadIdx.x;

    if (tid < 224u) {
        sbuf[4u + tid] = __ldg(x + (size_t)bc * ISTR + ih * 224u + tid);
    } else if (tid < 228u) {
        sbuf[tid - 224u] = 0.0f;          // left pad
    } else if (tid < 232u) {
        sbuf[tid] = 0.0f;                 // right pad
    }
    __syncthreads();

    unsigned w    = tid >> 5;             // 0..8
    unsigned lane = tid & 31u;
    unsigned ki   = w / 3u;
    unsigned kj   = w - ki * 3u;
    unsigned ck   = bc * 9u + w;
    int shift     = (int)kj - 1;
    int oh        = (int)ih + 1 - (int)ki;

    const float4* sm4 = (const float4*)sbuf;

    if ((unsigned)oh < 223u) {
        size_t d0     = (size_t)ck * OSP + (unsigned)oh * 223u;
        unsigned head = (unsigned)((4u - ((unsigned)d0 & 3u)) & 3u);
        int o     = (int)head + shift;    // [-1, 4]
        int dlt   = o & 3;
        int jbase = (o - dlt) >> 2;       // -1, 0, or 1
        float* dst   = out + d0;
        float4* dst4 = (float4*)(dst + head);

        // 3 scalar edge elements (head + tail); sbuf pads absorb iw=-1
        if (lane < 3u) {
            unsigned ow = (lane < head) ? lane : (head + 220u + (lane - head));
            __stcs(dst + ow, sbuf[4 + (int)ow + shift]);
        }

        // 55 aligned float4 stores; source = aligned LDS.128 pair + uniform select
        unsigned j0 = lane;               // < 32
        unsigned j1 = lane + 32u;         // valid if < 55
        int ia0 = (int)j0 + 1 + jbase, ia1 = (int)j1 + 1 + jbase;

        switch (dlt) {
        case 0: {
            float4 a0 = sm4[ia0];
            __stcs(dst4 + j0, a0);
            if (j1 < 55u) { float4 a1 = sm4[ia1]; __stcs(dst4 + j1, a1); }
        } break;
        case 1: {
            float4 a0 = sm4[ia0], b0 = sm4[ia0 + 1];
            __stcs(dst4 + j0, make_float4(a0.y, a0.z, a0.w, b0.x));
            if (j1 < 55u) {
                float4 a1 = sm4[ia1], b1 = sm4[ia1 + 1];
                __stcs(dst4 + j1, make_float4(a1.y, a1.z, a1.w, b1.x));
            }
        } break;
        case 2: {
            float4 a0 = sm4[ia0], b0 = sm4[ia0 + 1];
            __stcs(dst4 + j0, make_float4(a0.z, a0.w, b0.x, b0.y));
            if (j1 < 55u) {
                float4 a1 = sm4[ia1], b1 = sm4[ia1 + 1];
                __stcs(dst4 + j1, make_float4(a1.z, a1.w, b1.x, b1.y));
            }
        } break;
        default: {
            float4 a0 = sm4[ia0], b0 = sm4[ia0 + 1];
            __stcs(dst4 + j0, make_float4(a0.w, b0.x, b0.y, b0.z));
            if (j1 < 55u) {
                float4 a1 = sm4[ia1], b1 = sm4[ia1 + 1];
                __stcs(dst4 + j1, make_float4(a1.w, b1.x, b1.y, b1.z));
            }
        } break;
        }
    }

    // The single all-zero output row per ki=0 plane (oh=0 sources ih=-1):
    // written by the ih==0 block's ki==0 warps.
    if (ih == 0u && ki == 0u) {
        float* dst = out + (size_t)ck * OSP;     // oh = 0
        for (unsigned ow = lane; ow < 223u; ow += 32u) {
            __stcs(dst + ow, 0.0f);
        }
    }
}

extern "C" void kernel_launch(void* const* d_in, const int* in_sizes, int n_in,
                              void* d_out, int out_size) {
    const float* x = (const float*)d_in[0];
    float* out = (float*)d_out;
    dim3 grid(224, 256);
    unfold_smem<<<grid, 288>>>(x, out);
}

// round 6
// speedup vs baseline: 2.4228x; 1.2091x over previous
#include <cuda_runtime.h>
#include <stdint.h>

// IN:  x (4, 64, 224, 224) fp32
// OUT: (4, 576, 223*223) fp32, plane ck = bc*9 + ki*3 + kj
// out[ck, oh*223+ow] = x[bc, oh+ki-1, ow+kj-1] (0 if OOB)
#define OSP   49729u      // 223*223
#define ISTR  50176u      // 224*224

// Block = (8-row output group g, bc). 9 warps = 9 (ki,kj) planes.
// Stages input rows ih in [g*8-1, g*8+9] (11 rows) in smem with zero pads.
__global__ void __launch_bounds__(288) unfold_chunk8(const float* __restrict__ x,
                                                     float* __restrict__ out) {
    __shared__ __align__(16) float sbuf[11][232];  // 4 zero pad | 224 | 4 zero pad
    unsigned g8  = blockIdx.x * 8u;                // first oh of this chunk
    unsigned bc  = blockIdx.y;
    unsigned tid = threadIdx.x;
    unsigned w = tid >> 5, lane = tid & 31u;

    // ---- stage 11 input rows (rows outside [0,224) -> zeros) ----
    for (unsigned sr = w; sr < 11u; sr += 9u) {
        int ih = (int)g8 - 1 + (int)sr;
        bool ok = (unsigned)ih < 224u;
        const float* srow = x + (size_t)bc * ISTR + (size_t)(ok ? ih : 0) * 224u;
        for (unsigned c = lane; c < 232u; c += 32u) {
            float v = 0.0f;
            if (ok && c >= 4u && c < 228u) v = __ldg(srow + (c - 4u));
            sbuf[sr][c] = v;
        }
    }
    __syncthreads();

    unsigned ki = w / 3u;
    unsigned kj = w - 3u * ki;
    unsigned ck = bc * 9u + w;
    unsigned nrows = (g8 + 8u <= 223u) ? 8u : (223u - g8);  // 8, last chunk 7

    for (unsigned r = 0; r < nrows; ++r) {
        unsigned oh = g8 + r;
        size_t   drow = (size_t)ck * OSP + (size_t)oh * 223u;
        unsigned s    = (unsigned)(drow & 3u);
        unsigned lead = (4u - s) & 3u;       // floats before 16B boundary
        unsigned tail = 3u - lead;           // row floats after last in-row f4 (0..3)
        unsigned sr   = r + ki;              // smem source row
        unsigned off  = lead + kj + 3u;      // smem float idx of first in-row f4 elem
        unsigned dlt  = off & 3u;            // uniform per row
        unsigned jb   = off >> 2;
        const float4* sm4 = (const float4*)sbuf[sr];
        float4* dst4 = (float4*)(out + drow + lead);

        // 55 fully-in-row aligned float4 stores
        for (unsigned j = lane; j < 55u; j += 32u) {
            float4 a = sm4[jb + j];
            float4 b = sm4[jb + j + 1u];
            float4 v;
            switch (dlt) {
              case 0:  v = a; break;
              case 1:  v = make_float4(a.y, a.z, a.w, b.x); break;
              case 2:  v = make_float4(a.z, a.w, b.x, b.y); break;
              default: v = make_float4(a.w, b.x, b.y, b.z); break;
            }
            __stcs(dst4 + j, v);
        }

        // straddle f4 across row boundary (tail of row r + lead of row r+1)
        if (lane == 0u && tail != 0u && oh < 222u) {
            float vv[4];
#pragma unroll
            for (unsigned t = 0; t < 4u; ++t) {
                vv[t] = (t < tail) ? sbuf[sr][off + 220u + t]
                                   : sbuf[sr + 1u][(t - tail) + kj + 3u];
            }
            __stcs((float4*)(out + drow + lead + 220u),
                   make_float4(vv[0], vv[1], vv[2], vv[3]));
        }

        // plane-end tail scalars (only oh == 222)
        if (oh == 222u && lane < tail) {
            __stcs(out + drow + lead + 220u + lane, sbuf[sr][off + 220u + lane]);
        }

        // plane-start head scalars (only first chunk, first row)
        if (g8 == 0u && r == 0u && lane < lead) {
            __stcs(out + drow + lane, sbuf[sr][lane + kj + 3u]);
        }
    }
}

extern "C" void kernel_launch(void* const* d_in, const int* in_sizes, int n_in,
                              void* d_out, int out_size) {
    const float* x = (const float*)d_in[0];
    float* out = (float*)d_out;
    dim3 grid(28, 256);   // 28 row-groups (27*8 + 7), 256 bc planes
    unfold_chunk8<<<grid, 288>>>(x, out);
}